// round 11
// baseline (speedup 1.0000x reference)
#include <cuda_runtime.h>
#include <cuda_fp16.h>
#include <cstdint>

#define N_NODES 100000
#define N_EDGES 1600000
#define CH      128

typedef unsigned long long ull;

// Scratch (static device globals — no allocation in kernel_launch)
__device__ __align__(16) __half g_h16[(size_t)N_NODES * CH];  // 25.6 MB fp16 h
__device__ int g_deg[N_NODES];
__device__ int g_any_hi;   // statically 0; reset by k_sniff_fin each replay
__device__ int g_is64;     // 1 if edge_index is int64

// --------------------------------------- sniff dtype + init degree (fused) --
__global__ void k_sniff_deg(const int* __restrict__ w) {
    int t = blockIdx.x * blockDim.x + threadIdx.x;      // 100096 threads
    if (t < N_NODES) g_deg[t] = 1;
    int i = (int)(((long long)t * 1599983LL) % 1600000LL);
    if (w[2 * i + 1] != 0) g_any_hi = 1;
}

__global__ void k_sniff_fin() {
    g_is64 = (g_any_hi == 0);
    g_any_hi = 0;                       // reset for next graph replay
}

__device__ __forceinline__ void edge_params(int* stride, int* dbase) {
    int f = g_is64;
    *stride = f ? 2 : 1;
    *dbase  = f ? 2 * N_EDGES : N_EDGES;
}

// ---------------------------------------------------------------- degree ----
__global__ void k_deg_count(const int* __restrict__ ei) {
    int e = blockIdx.x * blockDim.x + threadIdx.x;
    if (e >= N_EDGES) return;
    int stride, dbase; edge_params(&stride, &dbase);
    atomicAdd(&g_deg[ei[dbase + stride * e]], 1);
}

// ------------------------------------------------------------------ GEMM ----
// h[m][o] = b[o] + sum_k x[m][k] * W[o][k]
// 128 threads, 4 warps, 32 rows/block (grid 3125).
// NEW mapping: warp w -> ALL 32 rows x cols [32w,32w+32). lane: r=lane>>3
// (8-row group), c=lane&7 (4-col group). b-quad: 8 distinct quads x 4-lane
// multicast = 128B = 1 wavefront (was 4). a-quad: 4 distinct rows x 8-lane
// multicast, xs quad-XOR swizzled (phys q = q ^ (row>>3)) -> conflict-free.
// Fused epilogue: out = h/deg (exact fp32), g_h16 = fp16(h).
__global__ void __launch_bounds__(128) k_gemm(const float* __restrict__ x,
                                              const float* __restrict__ W,
                                              const float* __restrict__ bias,
                                              float* __restrict__ out) {
    __shared__ float xs[32 * CH];  // quad-swizzled x tile (16 KB)
    __shared__ float wt[32][CH];   // wt[kk][o] = W[o][kc+kk] (16 KB)

    const int t    = threadIdx.x;
    const int w    = t >> 5;       // 0..3
    const int lane = t & 31;
    const int r    = lane >> 3;    // row group 0..3 (8 rows each)
    const int c    = lane & 7;     // col group 0..7 (4 cols each)
    const int ob   = w * 32 + c * 4;  // first output col for this lane

    // Load x tile, store quad-swizzled: phys quad = q ^ (row>>3)
    const float4* xg = (const float4*)(x + (size_t)blockIdx.x * 32 * CH);
    float4* xs4 = (float4*)xs;
    #pragma unroll
    for (int i = 0; i < 8; i++) {
        int v   = t + i * 128;
        int row = v >> 5, q = v & 31;
        xs4[row * 32 + (q ^ (row >> 3))] = xg[v];
    }

    float4 b4 = ((const float4*)bias)[w * 8 + c];
    ull acc[8][2];
    #pragma unroll
    for (int i = 0; i < 8; i++) {
        asm("mov.b64 %0, {%1, %2};" : "=l"(acc[i][0])
            : "r"(__float_as_uint(b4.x)), "r"(__float_as_uint(b4.y)));
        asm("mov.b64 %0, {%1, %2};" : "=l"(acc[i][1])
            : "r"(__float_as_uint(b4.z)), "r"(__float_as_uint(b4.w)));
    }

    for (int kc = 0; kc < CH; kc += 32) {
        __syncthreads();
        // thread t owns output col o=t: load its 32 k's, store transposed.
        #pragma unroll
        for (int i = 0; i < 8; i++) {
            float4 f = *(const float4*)(W + (size_t)t * CH + kc + i * 4);
            wt[i * 4 + 0][t] = f.x;
            wt[i * 4 + 1][t] = f.y;
            wt[i * 4 + 2][t] = f.z;
            wt[i * 4 + 3][t] = f.w;
        }
        __syncthreads();

        #pragma unroll
        for (int g = 0; g < 8; g++) {          // 4 k-steps per group
            const int k0 = g * 4;
            ulonglong2 bq0 = *(const ulonglong2*)&wt[k0 + 0][ob];  // 1 wf
            ulonglong2 bq1 = *(const ulonglong2*)&wt[k0 + 1][ob];
            ulonglong2 bq2 = *(const ulonglong2*)&wt[k0 + 2][ob];
            ulonglong2 bq3 = *(const ulonglong2*)&wt[k0 + 3][ob];
            const int qb = ((kc >> 2) + g) ^ r;   // swizzled quad index
            #pragma unroll
            for (int i = 0; i < 8; i++) {
                float4 a = xs4[(r * 8 + i) * 32 + qb];   // 1 wf (multicast)
                ull a0, a1, a2, a3;
                asm("mov.b64 %0, {%1, %1};" : "=l"(a0) : "r"(__float_as_uint(a.x)));
                asm("mov.b64 %0, {%1, %1};" : "=l"(a1) : "r"(__float_as_uint(a.y)));
                asm("mov.b64 %0, {%1, %1};" : "=l"(a2) : "r"(__float_as_uint(a.z)));
                asm("mov.b64 %0, {%1, %1};" : "=l"(a3) : "r"(__float_as_uint(a.w)));
                asm("fma.rn.f32x2 %0, %1, %2, %0;" : "+l"(acc[i][0]) : "l"(a0), "l"(bq0.x));
                asm("fma.rn.f32x2 %0, %1, %2, %0;" : "+l"(acc[i][1]) : "l"(a0), "l"(bq0.y));
                asm("fma.rn.f32x2 %0, %1, %2, %0;" : "+l"(acc[i][0]) : "l"(a1), "l"(bq1.x));
                asm("fma.rn.f32x2 %0, %1, %2, %0;" : "+l"(acc[i][1]) : "l"(a1), "l"(bq1.y));
                asm("fma.rn.f32x2 %0, %1, %2, %0;" : "+l"(acc[i][0]) : "l"(a2), "l"(bq2.x));
                asm("fma.rn.f32x2 %0, %1, %2, %0;" : "+l"(acc[i][1]) : "l"(a2), "l"(bq2.y));
                asm("fma.rn.f32x2 %0, %1, %2, %0;" : "+l"(acc[i][0]) : "l"(a3), "l"(bq3.x));
                asm("fma.rn.f32x2 %0, %1, %2, %0;" : "+l"(acc[i][1]) : "l"(a3), "l"(bq3.y));
            }
        }
    }

    // Epilogue: lane writes 8 rows x 4 cols at col block (w*8 + c)
    const size_t rowbase = (size_t)blockIdx.x * 32;
    #pragma unroll
    for (int i = 0; i < 8; i++) {
        int row = r * 8 + i;
        unsigned int r0, r1, r2, r3;
        asm("mov.b64 {%0, %1}, %2;" : "=r"(r0), "=r"(r1) : "l"(acc[i][0]));
        asm("mov.b64 {%0, %1}, %2;" : "=r"(r2), "=r"(r3) : "l"(acc[i][1]));
        float4 hv = make_float4(__uint_as_float(r0), __uint_as_float(r1),
                                __uint_as_float(r2), __uint_as_float(r3));
        size_t gidx = (rowbase + row) * 32 + w * 8 + c;

        __half2 p0 = __floats2half2_rn(hv.x, hv.y);
        __half2 p1 = __floats2half2_rn(hv.z, hv.w);
        uint2 pk;
        pk.x = *(unsigned int*)&p0;
        pk.y = *(unsigned int*)&p1;
        ((uint2*)g_h16)[gidx] = pk;

        float invd = 1.0f / (float)g_deg[rowbase + row];
        ((float4*)out)[gidx] =
            make_float4(hv.x * invd, hv.y * invd, hv.z * invd, hv.w * invd);
    }
}

// ------------------------------------------------------------ edge scatter --
// One warp per edge. nrm computed by lane 0 only (saves 31/32 of MUFU+LDG),
// shfl-broadcast. Gather fp16 h[src], vector red.add.v4 into out[dst].
__global__ void __launch_bounds__(256) k_edges(const int* __restrict__ ei,
                                               float* __restrict__ out) {
    int e    = (blockIdx.x << 3) + (threadIdx.x >> 5);
    int lane = threadIdx.x & 31;
    if (e >= N_EDGES) return;

    int stride, dbase; edge_params(&stride, &dbase);
    int s = ei[stride * e];
    int d = ei[dbase + stride * e];

    float nrm = 0.f;
    if (lane == 0)
        nrm = rsqrtf((float)g_deg[s] * (float)g_deg[d]);
    nrm = __shfl_sync(0xffffffffu, nrm, 0);

    uint2 pk = ((const uint2*)g_h16)[(size_t)s * 32 + lane];
    float2 f0 = __half22float2(*(const __half2*)&pk.x);
    float2 f1 = __half22float2(*(const __half2*)&pk.y);

    float* p = out + (size_t)d * CH + lane * 4;      // 16B aligned
    asm volatile("red.global.add.v4.f32 [%0], {%1, %2, %3, %4};"
                 :: "l"(p), "f"(f0.x * nrm), "f"(f0.y * nrm),
                    "f"(f1.x * nrm), "f"(f1.y * nrm)
                 : "memory");
}

// ------------------------------------------------------------------- glue ---
extern "C" void kernel_launch(void* const* d_in, const int* in_sizes, int n_in,
                              void* d_out, int out_size) {
    const float* x  = (const float*)d_in[0];
    const int*   ei = (const int*)d_in[1];     // int32 or int64 (sniffed)
    const float* W  = (const float*)d_in[2];
    const float* b  = (const float*)d_in[3];
    float* out = (float*)d_out;

    k_sniff_deg<<<(N_NODES + 255) / 256, 256>>>(ei);   // launch 0
    k_sniff_fin<<<1, 1>>>();                           // launch 1
    k_deg_count<<<(N_EDGES + 255) / 256, 256>>>(ei);   // launch 2
    k_gemm<<<N_NODES / 32, 128>>>(x, W, b, out);       // launch 3 (profiled)
    k_edges<<<N_EDGES / 8, 256>>>(ei, out);            // launch 4
}